// round 6
// baseline (speedup 1.0000x reference)
#include <cuda_runtime.h>
#include <math.h>

// ---------------------------------------------------------------------------
// LLIE loss, fully fused into two streaming SSIM kernels + tiny epilogues.
// B=16, C=3, H=W=512. SSIM 7x7 valid out 506x506.
//  ssim0: SSIM(comp0,real0) + all three L1 terms (streams img,tgt,c1,r1)
//  ssim1: SSIM(img,target) + MSE(img,tgt) + hist(tgt) + light MSE(c2,r1)
// ---------------------------------------------------------------------------

#define IMG_W   512
#define IMG_HW  (512 * 512)
#define OUT_W   506
#define NBC     48
#define N3      12582912.0
#define NHW     4194304.0

// 0 ssim0, 1 ssim1, 2 l1(all), 5 mse light, 6 mse out, 7 color, 8 gan
__device__ double g_acc[9];
__device__ unsigned int g_hist[NBC * 256];

// ---------------- f32x2 packed helpers (sm_103a) ---------------------------
typedef unsigned long long u64t;
__device__ __forceinline__ u64t f2_pack(float x, float y) {
    u64t r; asm("mov.b64 %0,{%1,%2};" : "=l"(r) : "f"(x), "f"(y)); return r;
}
__device__ __forceinline__ void f2_unpack(u64t p, float& x, float& y) {
    asm("mov.b64 {%0,%1},%2;" : "=f"(x), "=f"(y) : "l"(p));
}
__device__ __forceinline__ u64t f2_add(u64t a, u64t b) {
    u64t d; asm("add.rn.f32x2 %0,%1,%2;" : "=l"(d) : "l"(a), "l"(b)); return d;
}
__device__ __forceinline__ u64t f2_fma(u64t a, u64t b, u64t c) {
    u64t d; asm("fma.rn.f32x2 %0,%1,%2,%3;" : "=l"(d) : "l"(a), "l"(b), "l"(c)); return d;
}

// ---------------------------------------------------------------------------
__device__ __forceinline__ float blockReduceSum(float v, float* red) {
    #pragma unroll
    for (int o = 16; o > 0; o >>= 1) v += __shfl_down_sync(0xffffffffu, v, o);
    int lane = threadIdx.x & 31, wid = threadIdx.x >> 5;
    if (lane == 0) red[wid] = v;
    __syncthreads();
    v = (threadIdx.x < (blockDim.x >> 5)) ? red[threadIdx.x] : 0.f;
    if (wid == 0) {
        #pragma unroll
        for (int o = 16; o > 0; o >>= 1) v += __shfl_down_sync(0xffffffffu, v, o);
    }
    __syncthreads();
    return v;
}

// ---------------------------------------------------------------------------
__global__ void init_kernel() {
    int i = blockIdx.x * blockDim.x + threadIdx.x;
    if (i < 9) g_acc[i] = 0.0;
    for (int j = i; j < NBC * 256; j += gridDim.x * blockDim.x) g_hist[j] = 0u;
}

// ---------------------------------------------------------------------------
// SSIM core: sliding vertical 7-row window (static register ring), 7-row
// double-buffered smem groups (1 barrier/group), cooperative slot loading.
// elem(xv, yv, off) is invoked exactly once per in-plane pixel during the
// prefetch phase (columns < 256 of this half-block, rows owned by this strip).
// Grid: (2 col-halves, 4 row strips of 127, 48 planes), 256 threads.
template <class ElemF>
__device__ __forceinline__ float ssim_core(
    const float* __restrict__ xr, const float* __restrict__ yr,
    float2 (&sbuf)[2][7][264], ElemF elem)
{
    const int tid = threadIdx.x;
    const int cb = blockIdx.x;
    const int c0 = cb << 8;
    const int R0 = blockIdx.y * 127;
    const int rows = min(127, OUT_W - R0);
    const int total = rows + 6;                       // 133 or 131
    const int elemRows = (blockIdx.y == 3) ? total : 127;
    const int ncols = cb ? 256 : 262;
    const int nslots = 7 * ncols;

    // fixed per-thread slot map: slot s -> (row j, col c) of a 7-row group
    int jj[8], cc[8];
    #pragma unroll
    for (int i = 0; i < 8; i++) {
        int s = tid + (i << 8);
        if (s < nslots) {
            int j = cb ? (s >> 8)
                       : (int)(((unsigned long long)s * 128071ull) >> 25); // s/262
            jj[i] = j; cc[i] = s - j * ncols;
        } else { jj[i] = -1; cc[i] = 0; }
    }

    u64t rgA[7], rgQ[7]; float rgXY[7];
    #pragma unroll
    for (int j = 0; j < 7; j++) { rgA[j] = 0ull; rgQ[j] = 0ull; rgXY[j] = 0.f; }
    u64t SA = 0ull, SQ = 0ull;
    float SXY = 0.f, local = 0.f;
    const u64t NEG1 = f2_pack(-1.f, -1.f);
    const int gc = c0 + tid;
    const bool compok = (gc < OUT_W);

    float rx[8], ry[8];
    auto prefetch = [&](int gr_) {
        #pragma unroll
        for (int i = 0; i < 8; i++) {
            int j_ = jj[i];
            if (j_ >= 0) {
                int rr_ = gr_ + j_;
                if (rr_ < total) {
                    long off = (long)rr_ * IMG_W + c0 + cc[i];
                    float xv = xr[off], yv = yr[off];
                    rx[i] = xv; ry[i] = yv;
                    if (cc[i] < 256 && rr_ < elemRows) elem(xv, yv, off);
                }
            }
        }
    };

    prefetch(0);
    const int ngroups = (total + 6) / 7;              // 19 or 20
    for (int g = 0; g < ngroups; g++) {
        const int gr = g * 7;
        const int buf = g & 1;
        #pragma unroll
        for (int i = 0; i < 8; i++)
            if (jj[i] >= 0 && gr + jj[i] < total)
                sbuf[buf][jj[i]][cc[i]] = make_float2(rx[i], ry[i]);
        __syncthreads();
        if (gr + 7 < total) prefetch(gr + 7);

        if (compok) {
            #pragma unroll
            for (int j = 0; j < 7; j++) {
                const int rr = gr + j;
                if (rr < total) {
                    u64t a01 = 0ull, q01 = 0ull;
                    float sxy = 0.f;
                    #pragma unroll
                    for (int k = 0; k < 7; k++) {
                        float2 v = sbuf[buf][j][tid + k];
                        u64t vv = f2_pack(v.x, v.y);
                        a01 = f2_add(a01, vv);
                        q01 = f2_fma(vv, vv, q01);
                        sxy = fmaf(v.x, v.y, sxy);
                    }
                    SA = f2_add(SA, a01); SA = f2_fma(rgA[j], NEG1, SA); rgA[j] = a01;
                    SQ = f2_add(SQ, q01); SQ = f2_fma(rgQ[j], NEG1, SQ); rgQ[j] = q01;
                    SXY += sxy - rgXY[j]; rgXY[j] = sxy;

                    if (rr >= 6) {
                        const float inv = 1.f / 49.f, COVN = 49.f / 48.f;
                        float S0, S1, S2, S3;
                        f2_unpack(SA, S0, S1);
                        f2_unpack(SQ, S2, S3);
                        float ux = S0 * inv, uy = S1 * inv;
                        float uxx = S2 * inv, uyy = S3 * inv, uxy = SXY * inv;
                        float vx  = COVN * fmaf(-ux, ux, uxx);
                        float vy  = COVN * fmaf(-uy, uy, uyy);
                        float vxy = COVN * fmaf(-ux, uy, uxy);
                        float num = fmaf(ux + ux, uy, 1e-4f) *
                                    fmaf(2.f, vxy, 9e-4f);
                        float den = fmaf(ux, ux, fmaf(uy, uy, 1e-4f)) *
                                    (vx + vy + 9e-4f);
                        local += __fdividef(num, den);
                    }
                }
            }
        }
    }
    return local;
}

// ---------------------------------------------------------------------------
// ssim0: SSIM(comp0, real0) + merged L1 (|c0-r0| + |img-c0*c1| + |tgt-r0*r1|)
__global__ __launch_bounds__(256, 3) void ssim0_kernel(
    const float* __restrict__ x, const float* __restrict__ y,
    const float* __restrict__ img, const float* __restrict__ tgt,
    const float* __restrict__ c1p, const float* __restrict__ r1p)
{
    __shared__ float2 sbuf[2][7][264];
    __shared__ float red[32];

    const int z = blockIdx.z;
    const int b = z / 3;
    const int R0 = blockIdx.y * 127;
    const long pbase = (long)z * IMG_HW + (long)R0 * IMG_W;
    const long sbase = (long)b * IMG_HW + (long)R0 * IMG_W;
    const float* xr = x + pbase;
    const float* yr = y + pbase;
    const float* ir = img + pbase;
    const float* tr = tgt + pbase;
    const float* c1r = c1p + sbase;
    const float* r1r = r1p + sbase;

    float s_l1 = 0.f;
    float local = ssim_core(xr, yr, sbuf,
        [&](float xv, float yv, long off) {
            float iv = ir[off], tv = tr[off];
            float c1v = c1r[off], r1v = r1r[off];
            s_l1 += fabsf(xv - yv) + fabsf(fmaf(-xv, c1v, iv))
                                   + fabsf(fmaf(-yv, r1v, tv));
        });

    float t;
    t = blockReduceSum(local, red); if (threadIdx.x == 0) atomicAdd(&g_acc[0], (double)t);
    t = blockReduceSum(s_l1, red);  if (threadIdx.x == 0) atomicAdd(&g_acc[2], (double)t);
}

// ---------------------------------------------------------------------------
// ssim1: SSIM(img, target) + MSE(img,tgt) + hist(tgt) + light MSE (ch0 only)
__global__ __launch_bounds__(256, 3) void ssim1_kernel(
    const float* __restrict__ x, const float* __restrict__ y,
    const float* __restrict__ c2p, const float* __restrict__ r1p)
{
    __shared__ float2 sbuf[2][7][264];
    __shared__ float red[32];
    __shared__ unsigned int shist[256];

    shist[threadIdx.x] = 0u;
    __syncthreads();

    const int z = blockIdx.z;
    const int b = z / 3;
    const bool doLight = (z == b * 3);     // channel 0 of each batch image
    const int R0 = blockIdx.y * 127;
    const long pbase = (long)z * IMG_HW + (long)R0 * IMG_W;
    const long sbase = (long)b * IMG_HW + (long)R0 * IMG_W;
    const float* xr = x + pbase;
    const float* yr = y + pbase;
    const float* c2r = c2p + sbase;
    const float* r1r = r1p + sbase;

    float s_mse = 0.f, s_light = 0.f;
    float local = ssim_core(xr, yr, sbuf,
        [&](float xv, float yv, long off) {
            float d_ = xv - yv; s_mse = fmaf(d_, d_, s_mse);
            int bin_ = (int)rintf(yv * 255.f);
            bin_ = min(max(bin_, 0), 255);
            atomicAdd(&shist[bin_], 1u);
            if (doLight) {
                float dl = c2r[off] - r1r[off];
                s_light = fmaf(dl, dl, s_light);
            }
        });

    float t;
    t = blockReduceSum(local, red); if (threadIdx.x == 0) atomicAdd(&g_acc[1], (double)t);
    t = blockReduceSum(s_mse, red); if (threadIdx.x == 0) atomicAdd(&g_acc[6], (double)t);
    if (doLight) {
        t = blockReduceSum(s_light, red);
        if (threadIdx.x == 0) atomicAdd(&g_acc[5], (double)t);
    }
    __syncthreads();
    atomicAdd(&g_hist[z * 256 + threadIdx.x], shist[threadIdx.x]);
}

// ---------------------------------------------------------------------------
__global__ __launch_bounds__(256) void color_gan_kernel(
    const float* __restrict__ color_hist, const float* __restrict__ score)
{
    __shared__ float red[32];
    const float invHW = 1.f / (float)IMG_HW;

    float cs = 0.f;
    for (int i = threadIdx.x; i < NBC * 256; i += 256)
        cs += fabsf(color_hist[i] - (float)g_hist[i] * invHW);

    float gs = 0.f;
    if (threadIdx.x < 16) {
        float zz = -score[threadIdx.x];
        gs = fmaxf(zz, 0.f) + log1pf(expf(-fabsf(zz)));
    }

    float t;
    t = blockReduceSum(cs, red); if (threadIdx.x == 0) g_acc[7] = (double)t;
    t = blockReduceSum(gs, red); if (threadIdx.x == 0) g_acc[8] = (double)t;
}

// ---------------------------------------------------------------------------
__global__ void finalize_kernel(float* out, int out_size) {
    if (threadIdx.x != 0 || blockIdx.x != 0) return;
    const double nS = 48.0 * 506.0 * 506.0;
    double ssim0 = g_acc[0] / nS;
    double ssim1 = g_acc[1] / nS;
    double r     = (1.0 - ssim0) + g_acc[2] / N3;
    double light = g_acc[5] / NHW;
    double color = g_acc[7] / (48.0 * 256.0);
    double outl  = (1.0 - ssim1) + g_acc[6] / N3;
    double gan   = g_acc[8] / 16.0;
    double loss  = r + light + 0.1 * color + outl + 0.05 * gan;

    float v[7] = {(float)loss, (float)loss, (float)r, (float)light,
                  (float)color, (float)outl, (float)gan};
    const float* src = (out_size == 6) ? (v + 1) : v;
    int n = out_size < 7 ? out_size : 7;
    for (int i = 0; i < n; i++) out[i] = src[i];
}

// ---------------------------------------------------------------------------
extern "C" void kernel_launch(void* const* d_in, const int* in_sizes, int n_in,
                              void* d_out, int out_size) {
    const float* img    = (const float*)d_in[0];
    const float* target = (const float*)d_in[1];
    const float* comp0  = (const float*)d_in[2];
    const float* comp1  = (const float*)d_in[3];
    const float* comp2  = (const float*)d_in[4];
    const float* real0  = (const float*)d_in[5];
    const float* real1  = (const float*)d_in[6];
    const float* chist  = (const float*)d_in[7];
    const float* score  = (const float*)d_in[8];
    float* out = (float*)d_out;

    init_kernel<<<48, 256>>>();

    dim3 sgrid(2, 4, NBC);
    ssim0_kernel<<<sgrid, 256>>>(comp0, real0, img, target, comp1, real1);
    ssim1_kernel<<<sgrid, 256>>>(img, target, comp2, real1);

    color_gan_kernel<<<1, 256>>>(chist, score);

    finalize_kernel<<<1, 32>>>(out, out_size);
}

// round 7
// speedup vs baseline: 1.2511x; 1.2511x over previous
#include <cuda_runtime.h>
#include <math.h>

// ---------------------------------------------------------------------------
// LLIE loss: 2x SSIM(7x7, valid) + fused elementwise reductions + histogram
// color loss + BCE GAN loss.  B=16, C=3, H=W=512. SSIM valid out 506x506.
// ---------------------------------------------------------------------------

#define IMG_W   512
#define IMG_HW  (512 * 512)
#define OUT_W   506
#define NBC     48
#define N3      12582912.0
#define NHW     4194304.0

// 0 ssim0, 1 ssim1, 2 l1(all), 5 mse light, 6 mse out, 7 color, 8 gan
__device__ double g_acc[9];
__device__ unsigned int g_hist[NBC * 256];

// ---------------- f32x2 packed helpers (sm_103a) ---------------------------
typedef unsigned long long u64t;
__device__ __forceinline__ u64t f2_pack(float x, float y) {
    u64t r; asm("mov.b64 %0,{%1,%2};" : "=l"(r) : "f"(x), "f"(y)); return r;
}
__device__ __forceinline__ void f2_unpack(u64t p, float& x, float& y) {
    asm("mov.b64 {%0,%1},%2;" : "=f"(x), "=f"(y) : "l"(p));
}
__device__ __forceinline__ u64t f2_add(u64t a, u64t b) {
    u64t d; asm("add.rn.f32x2 %0,%1,%2;" : "=l"(d) : "l"(a), "l"(b)); return d;
}
__device__ __forceinline__ u64t f2_fma(u64t a, u64t b, u64t c) {
    u64t d; asm("fma.rn.f32x2 %0,%1,%2,%3;" : "=l"(d) : "l"(a), "l"(b), "l"(c)); return d;
}

// ---------------------------------------------------------------------------
__device__ __forceinline__ float blockReduceSum(float v, float* red) {
    #pragma unroll
    for (int o = 16; o > 0; o >>= 1) v += __shfl_down_sync(0xffffffffu, v, o);
    int lane = threadIdx.x & 31, wid = threadIdx.x >> 5;
    if (lane == 0) red[wid] = v;
    __syncthreads();
    v = (threadIdx.x < (blockDim.x >> 5)) ? red[threadIdx.x] : 0.f;
    if (wid == 0) {
        #pragma unroll
        for (int o = 16; o > 0; o >>= 1) v += __shfl_down_sync(0xffffffffu, v, o);
    }
    __syncthreads();
    return v;
}

// ---------------------------------------------------------------------------
__global__ void init_kernel() {
    int i = blockIdx.x * blockDim.x + threadIdx.x;
    if (i < 9) g_acc[i] = 0.0;
    for (int j = i; j < NBC * 256; j += gridDim.x * blockDim.x) g_hist[j] = 0u;
}

// ---------------------------------------------------------------------------
// Sliding-window SSIM with (s,d) = (x+y, x-y) packed stats.
// Only 4 window stats needed: Ss, Sd, Sqs, Sqd. Per tap: LDS.64 + f32x2 add
// + f32x2 fma. Vertical 7-row window via static register ring. 7-row
// double-buffered smem groups: ONE barrier per group. Cooperative slot
// loading (256 threads load 7x262 or 7x256 slots).
// Grid: (2 col-halves, 4 row strips of 127, 48 planes), 256 threads.
__global__ __launch_bounds__(256, 3) void ssim_kernel(
    const float* __restrict__ x, const float* __restrict__ y, int which)
{
    __shared__ u64t sbuf[2][7][264];
    __shared__ float red[32];

    const int tid = threadIdx.x;
    const int cb = blockIdx.x;
    const int c0 = cb << 8;
    const int R0 = blockIdx.y * 127;
    const int rows = min(127, OUT_W - R0);
    const int total = rows + 6;                    // 133 or 131
    const int ncols = cb ? 256 : 262;
    const int nslots = 7 * ncols;
    const long pbase = (long)blockIdx.z * IMG_HW + (long)R0 * IMG_W;
    const float* xr = x + pbase;
    const float* yr = y + pbase;

    // fixed per-thread slot map: slot s -> (row j, col c) within a 7-row group
    int jj[8], cc[8];
    #pragma unroll
    for (int i = 0; i < 8; i++) {
        int s = tid + (i << 8);
        if (s < nslots) {
            int j = cb ? (s >> 8)
                       : (int)(((unsigned long long)s * 128071ull) >> 25); // s/262
            jj[i] = j; cc[i] = s - j * ncols;
        } else { jj[i] = -1; cc[i] = 0; }
    }

    u64t rgA[7], rgQ[7];
    #pragma unroll
    for (int j = 0; j < 7; j++) { rgA[j] = 0ull; rgQ[j] = 0ull; }
    u64t SA = 0ull, SQ = 0ull;
    float local = 0.f;
    const u64t NEG1 = f2_pack(-1.f, -1.f);
    const int gc = c0 + tid;
    const bool compok = (gc < OUT_W);

    u64t ru[8];

    #define PREFETCH(GR)                                                       \
    {                                                                          \
        const int gr_ = (GR);                                                  \
        _Pragma("unroll")                                                      \
        for (int i = 0; i < 8; i++) {                                          \
            int j_ = jj[i];                                                    \
            if (j_ >= 0) {                                                     \
                int rr_ = gr_ + j_;                                            \
                if (rr_ < total) {                                             \
                    long off = (long)rr_ * IMG_W + c0 + cc[i];                 \
                    float xv = xr[off], yv = yr[off];                          \
                    ru[i] = f2_pack(xv + yv, xv - yv);                         \
                }                                                              \
            }                                                                  \
        }                                                                      \
    }

    PREFETCH(0)
    const int ngroups = (total + 6) / 7;           // 19
    for (int g = 0; g < ngroups; g++) {
        const int gr = g * 7;
        const int buf = g & 1;
        #pragma unroll
        for (int i = 0; i < 8; i++)
            if (jj[i] >= 0 && gr + jj[i] < total)
                sbuf[buf][jj[i]][cc[i]] = ru[i];
        __syncthreads();
        if (gr + 7 < total) PREFETCH(gr + 7)

        if (compok) {
            #pragma unroll
            for (int j = 0; j < 7; j++) {
                const int rr = gr + j;
                if (rr < total) {
                    u64t a = 0ull, q = 0ull;
                    #pragma unroll
                    for (int k = 0; k < 7; k++) {
                        u64t v = sbuf[buf][j][tid + k];
                        a = f2_add(a, v);
                        q = f2_fma(v, v, q);
                    }
                    SA = f2_add(SA, a); SA = f2_fma(rgA[j], NEG1, SA); rgA[j] = a;
                    SQ = f2_add(SQ, q); SQ = f2_fma(rgQ[j], NEG1, SQ); rgQ[j] = q;

                    if (rr >= 6) {
                        // scaled SSIM: K = 2*49^2 cancels between num and den
                        const float C1K = 0.4802f;      // 1e-4 * 4802
                        const float C2K = 4.3218f;      // 9e-4 * 4802
                        const float CV  = 49.f / 48.f;
                        const float CV49 = CV * 49.f;
                        float Ss, Sd, Qs, Qd;
                        f2_unpack(SA, Ss, Sd);
                        f2_unpack(SQ, Qs, Qd);
                        float ps = Ss * Ss, pd = Sd * Sd;
                        float t1 = ps - pd, t2 = ps + pd;
                        float q1 = Qs - Qd, q2 = Qs + Qd;
                        float f1 = t1 + C1K;
                        float f3 = t2 + C1K;
                        float f2v = fmaf(CV49, q1, fmaf(-CV, t1, C2K));
                        float f4v = fmaf(CV49, q2, fmaf(-CV, t2, C2K));
                        local += __fdividef(f1 * f2v, f3 * f4v);
                    }
                }
            }
        }
    }
    #undef PREFETCH

    float tot = blockReduceSum(local, red);
    if (tid == 0) atomicAdd(&g_acc[which], (double)tot);
}

// ---------------------------------------------------------------------------
// Fused elementwise pass, float4: merged-L1 + MSEs + target histogram.
// grid.x = B * 64; each block handles 4096 pixels.
__global__ __launch_bounds__(256, 4) void elem_kernel(
    const float4* __restrict__ img,   const float4* __restrict__ target,
    const float4* __restrict__ comp0, const float4* __restrict__ comp1,
    const float4* __restrict__ comp2, const float4* __restrict__ real0,
    const float4* __restrict__ real1)
{
    __shared__ unsigned int shist[768];
    __shared__ float red[32];

    const int tid = threadIdx.x;
    for (int i = tid; i < 768; i += 256) shist[i] = 0u;
    __syncthreads();

    const int b = blockIdx.x >> 6;
    const int chunk = blockIdx.x & 63;
    const int HW4 = IMG_HW / 4;
    const long bHW4 = (long)b * HW4;
    const long b3HW4 = (long)b * 3 * HW4;

    float s_l1 = 0.f, s_light = 0.f, s_mse = 0.f;

    #pragma unroll
    for (int it = 0; it < 4; it++) {
        const int p = chunk * 1024 + it * 256 + tid;
        float4 r1v = real1[bHW4 + p];
        {
            float4 c2v = comp2[bHW4 + p];
            float d;
            d = c2v.x - r1v.x; s_light = fmaf(d, d, s_light);
            d = c2v.y - r1v.y; s_light = fmaf(d, d, s_light);
            d = c2v.z - r1v.z; s_light = fmaf(d, d, s_light);
            d = c2v.w - r1v.w; s_light = fmaf(d, d, s_light);
        }
        float4 c1v = comp1[bHW4 + p];
        #pragma unroll
        for (int c = 0; c < 3; c++) {
            const long idx = b3HW4 + (long)c * HW4 + p;
            float4 iv  = img[idx];
            float4 tv  = target[idx];
            float4 c0v = comp0[idx];
            float4 r0v = real0[idx];
            #define DO_COMP(ix, tx, c0x, r0x, c1x, r1x)                        \
            {                                                                  \
                s_l1 += fabsf((c0x) - (r0x))                                   \
                      + fabsf((ix) - (c0x) * (c1x))                            \
                      + fabsf((tx) - (r0x) * (r1x));                           \
                float d_ = (ix) - (tx); s_mse = fmaf(d_, d_, s_mse);           \
                int bin_ = (int)rintf((tx) * 255.f);                           \
                bin_ = min(max(bin_, 0), 255);                                 \
                atomicAdd(&shist[c * 256 + bin_], 1u);                         \
            }
            DO_COMP(iv.x, tv.x, c0v.x, r0v.x, c1v.x, r1v.x)
            DO_COMP(iv.y, tv.y, c0v.y, r0v.y, c1v.y, r1v.y)
            DO_COMP(iv.z, tv.z, c0v.z, r0v.z, c1v.z, r1v.z)
            DO_COMP(iv.w, tv.w, c0v.w, r0v.w, c1v.w, r1v.w)
            #undef DO_COMP
        }
    }

    float t;
    t = blockReduceSum(s_l1, red);    if (tid == 0) atomicAdd(&g_acc[2], (double)t);
    t = blockReduceSum(s_light, red); if (tid == 0) atomicAdd(&g_acc[5], (double)t);
    t = blockReduceSum(s_mse, red);   if (tid == 0) atomicAdd(&g_acc[6], (double)t);

    __syncthreads();
    for (int i = tid; i < 768; i += 256)
        atomicAdd(&g_hist[b * 768 + i], shist[i]);
}

// ---------------------------------------------------------------------------
// Color L1 spread over 48 blocks (one per (b,c) plane) + GAN in block 0.
__global__ __launch_bounds__(256) void color_gan_kernel(
    const float* __restrict__ color_hist, const float* __restrict__ score)
{
    __shared__ float red[32];
    const float invHW = 1.f / (float)IMG_HW;
    const int bc = blockIdx.x;

    float cs = fabsf(color_hist[bc * 256 + threadIdx.x]
                     - (float)g_hist[bc * 256 + threadIdx.x] * invHW);

    float t = blockReduceSum(cs, red);
    if (threadIdx.x == 0) atomicAdd(&g_acc[7], (double)t);

    if (bc == 0) {
        float gs = 0.f;
        if (threadIdx.x < 16) {
            float zz = -score[threadIdx.x];
            gs = fmaxf(zz, 0.f) + log1pf(expf(-fabsf(zz)));
        }
        t = blockReduceSum(gs, red);
        if (threadIdx.x == 0) atomicAdd(&g_acc[8], (double)t);
    }
}

// ---------------------------------------------------------------------------
__global__ void finalize_kernel(float* out, int out_size) {
    if (threadIdx.x != 0 || blockIdx.x != 0) return;
    const double nS = 48.0 * 506.0 * 506.0;
    double ssim0 = g_acc[0] / nS;
    double ssim1 = g_acc[1] / nS;
    double r     = (1.0 - ssim0) + g_acc[2] / N3;
    double light = g_acc[5] / NHW;
    double color = g_acc[7] / (48.0 * 256.0);
    double outl  = (1.0 - ssim1) + g_acc[6] / N3;
    double gan   = g_acc[8] / 16.0;
    double loss  = r + light + 0.1 * color + outl + 0.05 * gan;

    float v[7] = {(float)loss, (float)loss, (float)r, (float)light,
                  (float)color, (float)outl, (float)gan};
    const float* src = (out_size == 6) ? (v + 1) : v;
    int n = out_size < 7 ? out_size : 7;
    for (int i = 0; i < n; i++) out[i] = src[i];
}

// ---------------------------------------------------------------------------
extern "C" void kernel_launch(void* const* d_in, const int* in_sizes, int n_in,
                              void* d_out, int out_size) {
    const float* img    = (const float*)d_in[0];
    const float* target = (const float*)d_in[1];
    const float* comp0  = (const float*)d_in[2];
    const float* comp1  = (const float*)d_in[3];
    const float* comp2  = (const float*)d_in[4];
    const float* real0  = (const float*)d_in[5];
    const float* real1  = (const float*)d_in[6];
    const float* chist  = (const float*)d_in[7];
    const float* score  = (const float*)d_in[8];
    float* out = (float*)d_out;

    init_kernel<<<48, 256>>>();

    dim3 sgrid(2, 4, NBC);
    ssim_kernel<<<sgrid, 256>>>(comp0, real0, 0);
    ssim_kernel<<<sgrid, 256>>>(img, target, 1);

    elem_kernel<<<16 * 64, 256>>>(
        (const float4*)img, (const float4*)target, (const float4*)comp0,
        (const float4*)comp1, (const float4*)comp2, (const float4*)real0,
        (const float4*)real1);

    color_gan_kernel<<<48, 256>>>(chist, score);

    finalize_kernel<<<1, 32>>>(out, out_size);
}

// round 8
// speedup vs baseline: 1.9511x; 1.5595x over previous
#include <cuda_runtime.h>
#include <math.h>

// ---------------------------------------------------------------------------
// LLIE loss: 2x SSIM(7x7, valid) + fused elementwise reductions + histogram
// color loss + BCE GAN loss.  B=16, C=3, H=W=512. SSIM valid out 506x506.
// ---------------------------------------------------------------------------

#define IMG_W   512
#define IMG_HW  (512 * 512)
#define OUT_W   506
#define NBC     48
#define N3      12582912.0
#define NHW     4194304.0

// 0 ssim0, 1 ssim1, 2 l1(all), 5 mse light, 6 mse out, 7 color, 8 gan
__device__ double g_acc[9];
__device__ unsigned int g_hist[NBC * 256];

// ---------------- f32x2 packed helpers (sm_103a) ---------------------------
typedef unsigned long long u64t;
__device__ __forceinline__ u64t f2_pack(float x, float y) {
    u64t r; asm("mov.b64 %0,{%1,%2};" : "=l"(r) : "f"(x), "f"(y)); return r;
}
__device__ __forceinline__ void f2_unpack(u64t p, float& x, float& y) {
    asm("mov.b64 {%0,%1},%2;" : "=f"(x), "=f"(y) : "l"(p));
}
__device__ __forceinline__ u64t f2_add(u64t a, u64t b) {
    u64t d; asm("add.rn.f32x2 %0,%1,%2;" : "=l"(d) : "l"(a), "l"(b)); return d;
}
__device__ __forceinline__ u64t f2_fma(u64t a, u64t b, u64t c) {
    u64t d; asm("fma.rn.f32x2 %0,%1,%2,%3;" : "=l"(d) : "l"(a), "l"(b), "l"(c)); return d;
}

// ---------------------------------------------------------------------------
__device__ __forceinline__ float blockReduceSum(float v, float* red) {
    #pragma unroll
    for (int o = 16; o > 0; o >>= 1) v += __shfl_down_sync(0xffffffffu, v, o);
    int lane = threadIdx.x & 31, wid = threadIdx.x >> 5;
    if (lane == 0) red[wid] = v;
    __syncthreads();
    v = (threadIdx.x < (blockDim.x >> 5)) ? red[threadIdx.x] : 0.f;
    if (wid == 0) {
        #pragma unroll
        for (int o = 16; o > 0; o >>= 1) v += __shfl_down_sync(0xffffffffu, v, o);
    }
    __syncthreads();
    return v;
}

// ---------------------------------------------------------------------------
__global__ void init_kernel() {
    int i = blockIdx.x * blockDim.x + threadIdx.x;
    if (i < 9) g_acc[i] = 0.0;
    for (int j = i; j < NBC * 256; j += gridDim.x * blockDim.x) g_hist[j] = 0u;
}

// ---------------------------------------------------------------------------
// Sliding-window SSIM, 7-row grouped, (s,d)=(x+y,x-y) packed stats.
// Thread owns one column. Vertical 7-row window kept as running sums with a
// 7-deep static register ring. Per tap: LDS.64 + add.f32x2 + fma.f32x2.
// 7-row smem buffer, 2 barriers per group; next group's globals prefetched
// into registers between barriers.
// Grid: (2 col-halves, 4 row strips of 127, 48 planes), 288 threads
// (256 compute cols + 6 halo-loader lanes in warp 8).
__global__ __launch_bounds__(288) void ssim_kernel(
    const float* __restrict__ x, const float* __restrict__ y, int which)
{
    __shared__ u64t s[7][264];
    __shared__ float red[32];

    const int tid = threadIdx.x;
    const int c0 = blockIdx.x << 8;            // 0 or 256
    const int R0 = blockIdx.y * 127;           // output-row strip start
    const int rows = min(127, OUT_W - R0);     // 127 or 125
    const int total = rows + 6;                // input rows this strip
    const long base = (long)blockIdx.z * IMG_HW;
    const int gc = c0 + tid;                   // column owned / loaded
    const bool loadok = (c0 == 0) ? (tid < 262) : (tid < 256);
    const bool compok = (tid < 256) && (gc < OUT_W);

    const float* xr = x + base + (long)R0 * IMG_W;
    const float* yr = y + base + (long)R0 * IMG_W;

    // 7-deep register ring of horizontal window sums (packed s,d stats)
    u64t rgA[7], rgQ[7];
    #pragma unroll
    for (int j = 0; j < 7; j++) { rgA[j] = 0ull; rgQ[j] = 0ull; }
    u64t SA = 0ull, SQ = 0ull;
    float local = 0.f;
    const u64t NEG1 = f2_pack(-1.f, -1.f);

    // prefetch group 0 (rows 0..6 always < total)
    u64t ps[7];
    #pragma unroll
    for (int j = 0; j < 7; j++) {
        ps[j] = 0ull;
        if (loadok) {
            float xv = xr[(long)j * IMG_W + gc];
            float yv = yr[(long)j * IMG_W + gc];
            ps[j] = f2_pack(xv + yv, xv - yv);
        }
    }

    const int ngroups = (total + 6) / 7;       // 19
    for (int g = 0; g < ngroups; g++) {
        const int gr = g * 7;

        // store current group to smem
        if (loadok) {
            #pragma unroll
            for (int j = 0; j < 7; j++)
                if (gr + j < total) s[j][tid] = ps[j];
        }
        __syncthreads();

        // prefetch next group into registers
        {
            const int nb = gr + 7;
            if (loadok && nb < total) {
                #pragma unroll
                for (int j = 0; j < 7; j++) {
                    const int rr = nb + j;
                    if (rr < total) {
                        float xv = xr[(long)rr * IMG_W + gc];
                        float yv = yr[(long)rr * IMG_W + gc];
                        ps[j] = f2_pack(xv + yv, xv - yv);
                    }
                }
            }
        }

        // process 7 rows
        if (compok) {
            #pragma unroll
            for (int j = 0; j < 7; j++) {
                const int rr = gr + j;
                if (rr < total) {
                    u64t a = 0ull, q = 0ull;
                    #pragma unroll
                    for (int k = 0; k < 7; k++) {
                        u64t v = s[j][tid + k];
                        a = f2_add(a, v);
                        q = f2_fma(v, v, q);
                    }
                    SA = f2_add(SA, a); SA = f2_fma(rgA[j], NEG1, SA); rgA[j] = a;
                    SQ = f2_add(SQ, q); SQ = f2_fma(rgQ[j], NEG1, SQ); rgQ[j] = q;

                    if (rr >= 6) {
                        // scaled SSIM: factor 2*49^2 = 4802 cancels num/den
                        const float C1K = 0.4802f;      // 1e-4 * 4802
                        const float C2K = 4.3218f;      // 9e-4 * 4802
                        const float CV  = 49.f / 48.f;
                        const float CV49 = CV * 49.f;
                        float Ss, Sd, Qs, Qd;
                        f2_unpack(SA, Ss, Sd);
                        f2_unpack(SQ, Qs, Qd);
                        float ps2 = Ss * Ss, pd2 = Sd * Sd;
                        float t1 = ps2 - pd2, t2 = ps2 + pd2;
                        float q1 = Qs - Qd,  q2 = Qs + Qd;
                        float f1 = t1 + C1K;
                        float f3 = t2 + C1K;
                        float f2v = fmaf(CV49, q1, fmaf(-CV, t1, C2K));
                        float f4v = fmaf(CV49, q2, fmaf(-CV, t2, C2K));
                        local += __fdividef(f1 * f2v, f3 * f4v);
                    }
                }
            }
        }
        __syncthreads();   // protect smem reuse next group
    }

    float tot = blockReduceSum(local, red);
    if (tid == 0) atomicAdd(&g_acc[which], (double)tot);
}

// ---------------------------------------------------------------------------
// Fused elementwise pass, float4: merged-L1 + MSEs + target histogram.
// grid.x = B * 64; each block handles 4096 pixels.
__global__ __launch_bounds__(256, 4) void elem_kernel(
    const float4* __restrict__ img,   const float4* __restrict__ target,
    const float4* __restrict__ comp0, const float4* __restrict__ comp1,
    const float4* __restrict__ comp2, const float4* __restrict__ real0,
    const float4* __restrict__ real1)
{
    __shared__ unsigned int shist[768];
    __shared__ float red[32];

    const int tid = threadIdx.x;
    for (int i = tid; i < 768; i += 256) shist[i] = 0u;
    __syncthreads();

    const int b = blockIdx.x >> 6;
    const int chunk = blockIdx.x & 63;
    const int HW4 = IMG_HW / 4;
    const long bHW4 = (long)b * HW4;
    const long b3HW4 = (long)b * 3 * HW4;

    float s_l1 = 0.f, s_light = 0.f, s_mse = 0.f;

    #pragma unroll
    for (int it = 0; it < 4; it++) {
        const int p = chunk * 1024 + it * 256 + tid;
        float4 r1v = real1[bHW4 + p];
        {
            float4 c2v = comp2[bHW4 + p];
            float d;
            d = c2v.x - r1v.x; s_light = fmaf(d, d, s_light);
            d = c2v.y - r1v.y; s_light = fmaf(d, d, s_light);
            d = c2v.z - r1v.z; s_light = fmaf(d, d, s_light);
            d = c2v.w - r1v.w; s_light = fmaf(d, d, s_light);
        }
        float4 c1v = comp1[bHW4 + p];
        #pragma unroll
        for (int c = 0; c < 3; c++) {
            const long idx = b3HW4 + (long)c * HW4 + p;
            float4 iv  = img[idx];
            float4 tv  = target[idx];
            float4 c0v = comp0[idx];
            float4 r0v = real0[idx];
            #define DO_COMP(ix, tx, c0x, r0x, c1x, r1x)                        \
            {                                                                  \
                s_l1 += fabsf((c0x) - (r0x))                                   \
                      + fabsf((ix) - (c0x) * (c1x))                            \
                      + fabsf((tx) - (r0x) * (r1x));                           \
                float d_ = (ix) - (tx); s_mse = fmaf(d_, d_, s_mse);           \
                int bin_ = (int)rintf((tx) * 255.f);                           \
                bin_ = min(max(bin_, 0), 255);                                 \
                atomicAdd(&shist[c * 256 + bin_], 1u);                         \
            }
            DO_COMP(iv.x, tv.x, c0v.x, r0v.x, c1v.x, r1v.x)
            DO_COMP(iv.y, tv.y, c0v.y, r0v.y, c1v.y, r1v.y)
            DO_COMP(iv.z, tv.z, c0v.z, r0v.z, c1v.z, r1v.z)
            DO_COMP(iv.w, tv.w, c0v.w, r0v.w, c1v.w, r1v.w)
            #undef DO_COMP
        }
    }

    float t;
    t = blockReduceSum(s_l1, red);    if (tid == 0) atomicAdd(&g_acc[2], (double)t);
    t = blockReduceSum(s_light, red); if (tid == 0) atomicAdd(&g_acc[5], (double)t);
    t = blockReduceSum(s_mse, red);   if (tid == 0) atomicAdd(&g_acc[6], (double)t);

    __syncthreads();
    for (int i = tid; i < 768; i += 256)
        atomicAdd(&g_hist[b * 768 + i], shist[i]);
}

// ---------------------------------------------------------------------------
// Color L1 spread over 48 blocks (one per (b,c) plane) + GAN in block 0.
__global__ __launch_bounds__(256) void color_gan_kernel(
    const float* __restrict__ color_hist, const float* __restrict__ score)
{
    __shared__ float red[32];
    const float invHW = 1.f / (float)IMG_HW;
    const int bc = blockIdx.x;

    float cs = fabsf(color_hist[bc * 256 + threadIdx.x]
                     - (float)g_hist[bc * 256 + threadIdx.x] * invHW);

    float t = blockReduceSum(cs, red);
    if (threadIdx.x == 0) atomicAdd(&g_acc[7], (double)t);

    if (bc == 0) {
        float gs = 0.f;
        if (threadIdx.x < 16) {
            float zz = -score[threadIdx.x];
            gs = fmaxf(zz, 0.f) + log1pf(expf(-fabsf(zz)));
        }
        t = blockReduceSum(gs, red);
        if (threadIdx.x == 0) atomicAdd(&g_acc[8], (double)t);
    }
}

// ---------------------------------------------------------------------------
__global__ void finalize_kernel(float* out, int out_size) {
    if (threadIdx.x != 0 || blockIdx.x != 0) return;
    const double nS = 48.0 * 506.0 * 506.0;
    double ssim0 = g_acc[0] / nS;
    double ssim1 = g_acc[1] / nS;
    double r     = (1.0 - ssim0) + g_acc[2] / N3;
    double light = g_acc[5] / NHW;
    double color = g_acc[7] / (48.0 * 256.0);
    double outl  = (1.0 - ssim1) + g_acc[6] / N3;
    double gan   = g_acc[8] / 16.0;
    double loss  = r + light + 0.1 * color + outl + 0.05 * gan;

    float v[7] = {(float)loss, (float)loss, (float)r, (float)light,
                  (float)color, (float)outl, (float)gan};
    const float* src = (out_size == 6) ? (v + 1) : v;
    int n = out_size < 7 ? out_size : 7;
    for (int i = 0; i < n; i++) out[i] = src[i];
}

// ---------------------------------------------------------------------------
extern "C" void kernel_launch(void* const* d_in, const int* in_sizes, int n_in,
                              void* d_out, int out_size) {
    const float* img    = (const float*)d_in[0];
    const float* target = (const float*)d_in[1];
    const float* comp0  = (const float*)d_in[2];
    const float* comp1  = (const float*)d_in[3];
    const float* comp2  = (const float*)d_in[4];
    const float* real0  = (const float*)d_in[5];
    const float* real1  = (const float*)d_in[6];
    const float* chist  = (const float*)d_in[7];
    const float* score  = (const float*)d_in[8];
    float* out = (float*)d_out;

    init_kernel<<<48, 256>>>();

    dim3 sgrid(2, 4, NBC);
    ssim_kernel<<<sgrid, 288>>>(comp0, real0, 0);
    ssim_kernel<<<sgrid, 288>>>(img, target, 1);

    elem_kernel<<<16 * 64, 256>>>(
        (const float4*)img, (const float4*)target, (const float4*)comp0,
        (const float4*)comp1, (const float4*)comp2, (const float4*)real0,
        (const float4*)real1);

    color_gan_kernel<<<48, 256>>>(chist, score);

    finalize_kernel<<<1, 32>>>(out, out_size);
}